// round 6
// baseline (speedup 1.0000x reference)
#include <cuda_runtime.h>
#include <cuda_bf16.h>
#include <cstddef>

// B=8, C=1024, Ci=512, N=T*H*W=2048
constexpr int Bn   = 8;
constexpr int C    = 1024;
constexpr int Ci   = 512;
constexpr int NSP  = 2048;

constexpr int TPB      = 128;     // 4 warps, warp grid 2x2, warp tile 64x64
constexpr int SOFT_TPB = 256;
// bf16 smem tile strides
constexpr int ANS = 24;           // natural [row][k16] stride (bf16): 48B rows, 16B-aligned, ldsm-conflict-free
constexpr int ANE = 128 * ANS;    // 3072 bf16 per plane
constexpr int KMS = 136;          // k-major [k16][col128] stride (bf16): ldsm.trans conflict-free
constexpr int KME = 16 * KMS;     // 2176 bf16 per plane

// fp32 scratch
__device__ float d_proj[(size_t)Bn * (3 * Ci) * NSP];  // [g | theta | phi]
__device__ float d_f[(size_t)Bn * NSP * NSP];          // scores / probs
__device__ float d_y[(size_t)Bn * Ci * NSP];

// ---------------------------------------------------------------------------
__device__ __forceinline__ unsigned smaddr(const void* p) {
    return (unsigned)__cvta_generic_to_shared(p);
}
__device__ __forceinline__ void ldsm4(const void* p, unsigned& r0, unsigned& r1,
                                      unsigned& r2, unsigned& r3) {
    asm volatile("ldmatrix.sync.aligned.m8n8.x4.shared.b16 {%0,%1,%2,%3}, [%4];"
                 : "=r"(r0), "=r"(r1), "=r"(r2), "=r"(r3) : "r"(smaddr(p)));
}
__device__ __forceinline__ void ldsm4t(const void* p, unsigned& r0, unsigned& r1,
                                       unsigned& r2, unsigned& r3) {
    asm volatile("ldmatrix.sync.aligned.m8n8.x4.trans.shared.b16 {%0,%1,%2,%3}, [%4];"
                 : "=r"(r0), "=r"(r1), "=r"(r2), "=r"(r3) : "r"(smaddr(p)));
}
__device__ __forceinline__ void mma_bf(float* c, const unsigned* a, unsigned b0, unsigned b1) {
    asm volatile(
        "mma.sync.aligned.m16n8k16.row.col.f32.bf16.bf16.f32 "
        "{%0,%1,%2,%3}, {%4,%5,%6,%7}, {%8,%9}, {%0,%1,%2,%3};"
        : "+f"(c[0]), "+f"(c[1]), "+f"(c[2]), "+f"(c[3])
        : "r"(a[0]), "r"(a[1]), "r"(a[2]), "r"(a[3]), "r"(b0), "r"(b1));
}

// Split 4 fp32 into hi/lo bf16 quads.
__device__ __forceinline__ void split4(float4 v, uint2& h, uint2& l) {
    __nv_bfloat162 h0 = __floats2bfloat162_rn(v.x, v.y);
    __nv_bfloat162 h1 = __floats2bfloat162_rn(v.z, v.w);
    __nv_bfloat162 l0 = __floats2bfloat162_rn(v.x - __bfloat162float(h0.x),
                                              v.y - __bfloat162float(h0.y));
    __nv_bfloat162 l1 = __floats2bfloat162_rn(v.z - __bfloat162float(h1.x),
                                              v.w - __bfloat162float(h1.y));
    h.x = *reinterpret_cast<unsigned*>(&h0);
    h.y = *reinterpret_cast<unsigned*>(&h1);
    l.x = *reinterpret_cast<unsigned*>(&l0);
    l.y = *reinterpret_cast<unsigned*>(&l1);
}

// --- global loads: each thread fetches 16 consecutive fp32 ------------------
// natural row-major [128 rows][k16]: row = tid.
__device__ __forceinline__ void ldg_row16(const float* __restrict__ A, int lda,
                                          int tid, int kglob, float4* v) {
    const float* p = A + (size_t)tid * lda + kglob;
    v[0] = *(const float4*)(p);      v[1] = *(const float4*)(p + 4);
    v[2] = *(const float4*)(p + 8);  v[3] = *(const float4*)(p + 12);
}
// k-major [k16][128 cols]: k = tid>>3, col = (tid&7)*16.
__device__ __forceinline__ void ldg_col16(const float* __restrict__ B, int ldb,
                                          int tid, int kglob, int d0, float4* v) {
    const float* p = B + (size_t)(kglob + (tid >> 3)) * ldb + d0 + (tid & 7) * 16;
    v[0] = *(const float4*)(p);      v[1] = *(const float4*)(p + 4);
    v[2] = *(const float4*)(p + 8);  v[3] = *(const float4*)(p + 12);
}

// --- smem stores (hi/lo planes) --------------------------------------------
__device__ __forceinline__ void sts_row16(unsigned short* H, unsigned short* L,
                                          int tid, const float4* v) {
    const int idx = tid * ANS;
    uint2 h, l;
    #pragma unroll
    for (int q = 0; q < 4; ++q) {
        split4(v[q], h, l);
        *(uint2*)(H + idx + 4 * q) = h;
        *(uint2*)(L + idx + 4 * q) = l;
    }
}
__device__ __forceinline__ void sts_col16(unsigned short* H, unsigned short* L,
                                          int tid, const float4* v) {
    const int idx = (tid >> 3) * KMS + (tid & 7) * 16;
    uint2 h, l;
    #pragma unroll
    for (int q = 0; q < 4; ++q) {
        split4(v[q], h, l);
        *(uint2*)(H + idx + 4 * q) = h;
        *(uint2*)(L + idx + 4 * q) = l;
    }
}

// --- fragment gathers (all ldmatrix) ---------------------------------------
// A: AKM=false -> natural [m][k16] stride ANS (non-trans);
//    AKM=true  -> k-major [k16][m128] stride KMS (trans, reorder r1<->r2).
template<bool AKM>
__device__ __forceinline__ void frag_a(const unsigned short* S, int m_base,
                                       int lane, unsigned* a) {
    if (AKM) {
        const int k  = (lane & 7) + ((lane >> 3) & 1) * 8;
        const int mc = m_base + (lane >> 4) * 8;
        unsigned r0, r1, r2, r3;
        ldsm4t(S + k * KMS + mc, r0, r1, r2, r3);
        a[0] = r0; a[1] = r2; a[2] = r1; a[3] = r3;
    } else {
        const int row  = m_base + (lane & 15);
        const int kofs = (lane >> 4) * 8;
        ldsm4(S + row * ANS + kofs, a[0], a[1], a[2], a[3]);
    }
}
// B covering n16 (two adjacent j): returns {j0.b0, j0.b1, j1.b0, j1.b1}.
template<bool BKM>
__device__ __forceinline__ void frag_b(const unsigned short* S, int n_base,
                                       int lane, unsigned* b) {
    if (BKM) {
        const int k  = (lane & 7) + ((lane >> 3) & 1) * 8;
        const int nc = n_base + (lane >> 4) * 8;
        ldsm4t(S + k * KMS + nc, b[0], b[1], b[2], b[3]);
    } else {
        const int row  = n_base + ((lane >> 4) & 1) * 8 + (lane & 7);
        const int kofs = ((lane >> 3) & 1) * 8;
        ldsm4(S + row * ANS + kofs, b[0], b[1], b[2], b[3]);
    }
}

#define ACC_INIT(acc)                                        \
    float acc[4][8][4];                                      \
    _Pragma("unroll") for (int i = 0; i < 4; ++i)            \
    _Pragma("unroll") for (int j = 0; j < 8; ++j)            \
    _Pragma("unroll") for (int q = 0; q < 4; ++q) acc[i][j][q] = 0.f;

// 3xBF16 64x64 warp-tile compute for one k16 slice.
template<bool AKM, bool BKM>
__device__ __forceinline__ void comp64(const unsigned short* Ah, const unsigned short* Al,
                                       const unsigned short* Bh, const unsigned short* Bl,
                                       int lane, int wm, int wn, float (&acc)[4][8][4]) {
    unsigned ah[4][4], al[4][4];
    #pragma unroll
    for (int i = 0; i < 4; ++i) {
        frag_a<AKM>(Ah, wm + i * 16, lane, ah[i]);
        frag_a<AKM>(Al, wm + i * 16, lane, al[i]);
    }
    #pragma unroll
    for (int jj = 0; jj < 4; ++jj) {
        unsigned bh[4], bl[4];
        frag_b<BKM>(Bh, wn + jj * 16, lane, bh);
        frag_b<BKM>(Bl, wn + jj * 16, lane, bl);
        #pragma unroll
        for (int jr = 0; jr < 2; ++jr) {
            const int j = jj * 2 + jr;
            #pragma unroll
            for (int i = 0; i < 4; ++i) {
                mma_bf(acc[i][j], ah[i], bh[jr*2], bh[jr*2+1]);
                mma_bf(acc[i][j], ah[i], bl[jr*2], bl[jr*2+1]);
                mma_bf(acc[i][j], al[i], bh[jr*2], bh[jr*2+1]);
            }
        }
    }
}

// ---------------------------------------------------------------------------
// Kernel 1: projections. proj[b][o][n] = sum_c W[o][c] x[b][c][n] + bias[o]
// ---------------------------------------------------------------------------
__global__ __launch_bounds__(TPB)
void k_proj(const float* __restrict__ x,
            const float* __restrict__ gw, const float* __restrict__ gb,
            const float* __restrict__ tw, const float* __restrict__ tb,
            const float* __restrict__ pw, const float* __restrict__ pb)
{
    __shared__ __align__(16) unsigned short Ah[2][ANE], Al[2][ANE];
    __shared__ __align__(16) unsigned short Bh[2][KME], Bl[2][KME];

    const int tid = threadIdx.x, lane = tid & 31, wid = tid >> 5;
    const int wm = (wid >> 1) * 64, wn = (wid & 1) * 64;
    const int n0 = blockIdx.x * 128;
    const int mt = blockIdx.y;             // 0..11
    const int b  = blockIdx.z;

    const float *W, *bias;
    if (mt < 4)      { W = gw; bias = gb; }
    else if (mt < 8) { W = tw; bias = tb; }
    else             { W = pw; bias = pb; }
    const int mloc = (mt & 3) * 128;

    const float* Aptr = W + (size_t)mloc * C;
    const float* Bptr = x + (size_t)b * C * NSP;
    float*       Cptr = d_proj + ((size_t)b * (3 * Ci) + (size_t)mt * 128) * NSP;

    float4 va[4], vb[4];
    ldg_row16(Aptr, C, tid, 0, va);
    ldg_col16(Bptr, NSP, tid, 0, n0, vb);
    sts_row16(Ah[0], Al[0], tid, va);
    sts_col16(Bh[0], Bl[0], tid, vb);
    __syncthreads();

    ACC_INIT(acc);
    const int KT = C / 16;                 // 64
    for (int kt = 0; kt < KT; ++kt) {
        const int buf = kt & 1;
        const bool more = (kt + 1 < KT);
        if (more) {
            ldg_row16(Aptr, C, tid, (kt + 1) * 16, va);
            ldg_col16(Bptr, NSP, tid, (kt + 1) * 16, n0, vb);
        }
        comp64<false, true>(Ah[buf], Al[buf], Bh[buf], Bl[buf], lane, wm, wn, acc);
        if (more) {
            sts_row16(Ah[buf ^ 1], Al[buf ^ 1], tid, va);
            sts_col16(Bh[buf ^ 1], Bl[buf ^ 1], tid, vb);
        }
        __syncthreads();
    }

    const int gid = lane >> 2, tig = lane & 3;
    #pragma unroll
    for (int i = 0; i < 4; ++i) {
        const int r = wm + i * 16 + gid;
        const float bv0 = bias[mloc + r], bv1 = bias[mloc + r + 8];
        #pragma unroll
        for (int j = 0; j < 8; ++j) {
            const int col = n0 + wn + j * 8 + tig * 2;
            float2 o0 = { acc[i][j][0] + bv0, acc[i][j][1] + bv0 };
            float2 o1 = { acc[i][j][2] + bv1, acc[i][j][3] + bv1 };
            *(float2*)(Cptr + (size_t)r * NSP + col)       = o0;
            *(float2*)(Cptr + (size_t)(r + 8) * NSP + col) = o1;
        }
    }
}

// ---------------------------------------------------------------------------
// Kernel 2: scores. f[b][n][m] = sum_c theta[b][c][n] phi[b][c][m]
// ---------------------------------------------------------------------------
__global__ __launch_bounds__(TPB)
void k_scores()
{
    __shared__ __align__(16) unsigned short Ah[2][KME], Al[2][KME];
    __shared__ __align__(16) unsigned short Bh[2][KME], Bl[2][KME];

    const int tid = threadIdx.x, lane = tid & 31, wid = tid >> 5;
    const int wm = (wid >> 1) * 64, wn = (wid & 1) * 64;
    const int m0 = blockIdx.x * 128;
    const int r0 = blockIdx.y * 128;
    const int b  = blockIdx.z;

    const float* Aptr = d_proj + ((size_t)b * (3 * Ci) + Ci)     * NSP; // theta
    const float* Bptr = d_proj + ((size_t)b * (3 * Ci) + 2 * Ci) * NSP; // phi
    float*       Cptr = d_f + (size_t)b * NSP * NSP;

    float4 va[4], vb[4];
    ldg_col16(Aptr, NSP, tid, 0, r0, va);
    ldg_col16(Bptr, NSP, tid, 0, m0, vb);
    sts_col16(Ah[0], Al[0], tid, va);
    sts_col16(Bh[0], Bl[0], tid, vb);
    __syncthreads();

    ACC_INIT(acc);
    const int KT = Ci / 16;                // 32
    for (int kt = 0; kt < KT; ++kt) {
        const int buf = kt & 1;
        const bool more = (kt + 1 < KT);
        if (more) {
            ldg_col16(Aptr, NSP, tid, (kt + 1) * 16, r0, va);
            ldg_col16(Bptr, NSP, tid, (kt + 1) * 16, m0, vb);
        }
        comp64<true, true>(Ah[buf], Al[buf], Bh[buf], Bl[buf], lane, wm, wn, acc);
        if (more) {
            sts_col16(Ah[buf ^ 1], Al[buf ^ 1], tid, va);
            sts_col16(Bh[buf ^ 1], Bl[buf ^ 1], tid, vb);
        }
        __syncthreads();
    }

    const int gid = lane >> 2, tig = lane & 3;
    #pragma unroll
    for (int i = 0; i < 4; ++i) {
        const int r = r0 + wm + i * 16 + gid;
        #pragma unroll
        for (int j = 0; j < 8; ++j) {
            const int col = m0 + wn + j * 8 + tig * 2;
            *(float2*)(Cptr + (size_t)r * NSP + col)       = *(float2*)&acc[i][j][0];
            *(float2*)(Cptr + (size_t)(r + 8) * NSP + col) = *(float2*)&acc[i][j][2];
        }
    }
}

// ---------------------------------------------------------------------------
// Kernel 3: row softmax in place on d_f.
// ---------------------------------------------------------------------------
__global__ __launch_bounds__(SOFT_TPB)
void k_softmax()
{
    const int tid = threadIdx.x;
    float* row = d_f + (size_t)blockIdx.x * NSP;

    float v[8];
    #pragma unroll
    for (int i = 0; i < 8; i++) v[i] = row[tid + 256 * i];

    float m = v[0];
    #pragma unroll
    for (int i = 1; i < 8; i++) m = fmaxf(m, v[i]);
    #pragma unroll
    for (int o = 16; o; o >>= 1) m = fmaxf(m, __shfl_xor_sync(0xffffffffu, m, o));

    __shared__ float redm[8], reds[8];
    const int wid = tid >> 5, lane = tid & 31;
    if (lane == 0) redm[wid] = m;
    __syncthreads();
    m = redm[0];
    #pragma unroll
    for (int i = 1; i < 8; i++) m = fmaxf(m, redm[i]);

    float s = 0.f;
    #pragma unroll
    for (int i = 0; i < 8; i++) { v[i] = __expf(v[i] - m); s += v[i]; }
    #pragma unroll
    for (int o = 16; o; o >>= 1) s += __shfl_xor_sync(0xffffffffu, s, o);
    if (lane == 0) reds[wid] = s;
    __syncthreads();
    s = reds[0];
    #pragma unroll
    for (int i = 1; i < 8; i++) s += reds[i];

    const float inv = 1.0f / s;
    #pragma unroll
    for (int i = 0; i < 8; i++) row[tid + 256 * i] = v[i] * inv;
}

// ---------------------------------------------------------------------------
// Kernel 4: apply. y[b][ci][n] = sum_m g[b][ci][m] P[b][n][m]
// A = g natural (k=m contiguous). B = P natural [n][k=m].
// ---------------------------------------------------------------------------
__global__ __launch_bounds__(TPB)
void k_ygemm()
{
    __shared__ __align__(16) unsigned short Ah[2][ANE], Al[2][ANE];
    __shared__ __align__(16) unsigned short Ph[2][ANE], Pl[2][ANE];

    const int tid = threadIdx.x, lane = tid & 31, wid = tid >> 5;
    const int wm = (wid >> 1) * 64, wn = (wid & 1) * 64;
    const int n0 = blockIdx.x * 128;
    const int c0 = blockIdx.y * 128;
    const int b  = blockIdx.z;

    const float* Aptr = d_proj + (size_t)b * (3 * Ci) * NSP + (size_t)c0 * NSP; // g
    const float* Bptr = d_f + (size_t)b * NSP * NSP + (size_t)n0 * NSP;         // P rows n0..
    float*       Cptr = d_y + (size_t)b * Ci * NSP;

    float4 va[4], vb[4];
    ldg_row16(Aptr, NSP, tid, 0, va);
    ldg_row16(Bptr, NSP, tid, 0, vb);
    sts_row16(Ah[0], Al[0], tid, va);
    sts_row16(Ph[0], Pl[0], tid, vb);
    __syncthreads();

    ACC_INIT(acc);
    const int KT = NSP / 16;               // 128
    for (int kt = 0; kt < KT; ++kt) {
        const int buf = kt & 1;
        const bool more = (kt + 1 < KT);
        if (more) {
            ldg_row16(Aptr, NSP, tid, (kt + 1) * 16, va);
            ldg_row16(Bptr, NSP, tid, (kt + 1) * 16, vb);
        }
        comp64<false, false>(Ah[buf], Al[buf], Ph[buf], Pl[buf], lane, wm, wn, acc);
        if (more) {
            sts_row16(Ah[buf ^ 1], Al[buf ^ 1], tid, va);
            sts_row16(Ph[buf ^ 1], Pl[buf ^ 1], tid, vb);
        }
        __syncthreads();
    }

    const int gid = lane >> 2, tig = lane & 3;
    #pragma unroll
    for (int i = 0; i < 4; ++i) {
        const int r = c0 + wm + i * 16 + gid;
        #pragma unroll
        for (int j = 0; j < 8; ++j) {
            const int col = n0 + wn + j * 8 + tig * 2;
            *(float2*)(Cptr + (size_t)r * NSP + col)       = *(float2*)&acc[i][j][0];
            *(float2*)(Cptr + (size_t)(r + 8) * NSP + col) = *(float2*)&acc[i][j][2];
        }
    }
}

// ---------------------------------------------------------------------------
// Kernel 5: out GEMM + bias + BN + residual.
// ---------------------------------------------------------------------------
__global__ __launch_bounds__(TPB)
void k_final(const float* __restrict__ Ww, const float* __restrict__ Wb,
             const float* __restrict__ gamma, const float* __restrict__ beta,
             const float* __restrict__ mean,  const float* __restrict__ var,
             const float* __restrict__ x, float* __restrict__ out)
{
    __shared__ __align__(16) unsigned short Ah[2][ANE], Al[2][ANE];
    __shared__ __align__(16) unsigned short Bh[2][KME], Bl[2][KME];

    const int tid = threadIdx.x, lane = tid & 31, wid = tid >> 5;
    const int wm = (wid >> 1) * 64, wn = (wid & 1) * 64;
    const int n0 = blockIdx.x * 128;
    const int c0 = blockIdx.y * 128;
    const int b  = blockIdx.z;

    const float* Aptr = Ww + (size_t)c0 * Ci;
    const float* Bptr = d_y + (size_t)b * Ci * NSP;

    float4 va[4], vb[4];
    ldg_row16(Aptr, Ci, tid, 0, va);
    ldg_col16(Bptr, NSP, tid, 0, n0, vb);
    sts_row16(Ah[0], Al[0], tid, va);
    sts_col16(Bh[0], Bl[0], tid, vb);
    __syncthreads();

    ACC_INIT(acc);
    const int KT = Ci / 16;                // 32
    for (int kt = 0; kt < KT; ++kt) {
        const int buf = kt & 1;
        const bool more = (kt + 1 < KT);
        if (more) {
            ldg_row16(Aptr, Ci, tid, (kt + 1) * 16, va);
            ldg_col16(Bptr, NSP, tid, (kt + 1) * 16, n0, vb);
        }
        comp64<false, true>(Ah[buf], Al[buf], Bh[buf], Bl[buf], lane, wm, wn, acc);
        if (more) {
            sts_row16(Ah[buf ^ 1], Al[buf ^ 1], tid, va);
            sts_col16(Bh[buf ^ 1], Bl[buf ^ 1], tid, vb);
        }
        __syncthreads();
    }

    const int gid = lane >> 2, tig = lane & 3;
    #pragma unroll
    for (int i = 0; i < 4; ++i) {
        const int ch0 = c0 + wm + i * 16 + gid;
        const int ch1 = ch0 + 8;
        const float sg0 = rsqrtf(var[ch0] + 1e-5f) * gamma[ch0];
        const float of0 = (Wb[ch0] - mean[ch0]) * sg0 + beta[ch0];
        const float sg1 = rsqrtf(var[ch1] + 1e-5f) * gamma[ch1];
        const float of1 = (Wb[ch1] - mean[ch1]) * sg1 + beta[ch1];
        #pragma unroll
        for (int j = 0; j < 8; ++j) {
            const int col = n0 + wn + j * 8 + tig * 2;
            const size_t p0 = ((size_t)b * C + ch0) * NSP + col;
            const size_t p1 = ((size_t)b * C + ch1) * NSP + col;
            const float2 x0 = *(const float2*)(x + p0);
            const float2 x1 = *(const float2*)(x + p1);
            float2 o0 = { acc[i][j][0] * sg0 + of0 + x0.x,
                          acc[i][j][1] * sg0 + of0 + x0.y };
            float2 o1 = { acc[i][j][2] * sg1 + of1 + x1.x,
                          acc[i][j][3] * sg1 + of1 + x1.y };
            *(float2*)(out + p0) = o0;
            *(float2*)(out + p1) = o1;
        }
    }
}

// ---------------------------------------------------------------------------
extern "C" void kernel_launch(void* const* d_in, const int* in_sizes, int n_in,
                              void* d_out, int out_size)
{
    const float* x     = (const float*)d_in[0];
    const float* g_w   = (const float*)d_in[1];
    const float* g_b   = (const float*)d_in[2];
    const float* th_w  = (const float*)d_in[3];
    const float* th_b  = (const float*)d_in[4];
    const float* ph_w  = (const float*)d_in[5];
    const float* ph_b  = (const float*)d_in[6];
    const float* W_w   = (const float*)d_in[7];
    const float* W_b   = (const float*)d_in[8];
    const float* gamma = (const float*)d_in[9];
    const float* beta  = (const float*)d_in[10];
    const float* mean  = (const float*)d_in[11];
    const float* var   = (const float*)d_in[12];
    float* out = (float*)d_out;

    k_proj   <<<dim3(NSP / 128, 12, Bn), TPB>>>(x, g_w, g_b, th_w, th_b, ph_w, ph_b);
    k_scores <<<dim3(NSP / 128, NSP / 128, Bn), TPB>>>();
    k_softmax<<<dim3(Bn * NSP), SOFT_TPB>>>();
    k_ygemm  <<<dim3(NSP / 128, Ci / 128, Bn), TPB>>>();
    k_final  <<<dim3(NSP / 128, C / 128, Bn), TPB>>>(W_w, W_b, gamma, beta, mean, var, x, out);
}